// round 17
// baseline (speedup 1.0000x reference)
#include <cuda_runtime.h>
#include <cuda_fp16.h>
#include <cstdint>
#include <cmath>

#define NB     4
#define LQ     4096
#define LKV    512
#define DATTN  1024
#define NHEADS 16
#define HDIM   64

// Scratch (device globals: allocation-free rule)
__device__ float  g_qh[NB * LQ * DATTN];         // 64 MB (fp32, attn input)
__device__ float  g_kv[NB * LKV * 2 * DATTN];    // 16 MB (fp32, attn input)
__device__ __half g_attn[NB * LQ * DATTN];       // 32 MB (fp16, G3 A operand)
// fp16-converted GEMM operands
__device__ __half g_qr[NB * LQ * 1024];
__device__ __half g_kvsr[NB * LKV * 1024];
__device__ __half g_wq[DATTN * 1024];
__device__ __half g_wkv[2 * DATTN * 1024];
__device__ __half g_wo[1024 * DATTN];

__device__ __forceinline__ void mma16(float* d, const uint32_t* a, const uint32_t* b) {
    asm volatile(
        "mma.sync.aligned.m16n8k16.row.col.f32.f16.f16.f32 "
        "{%0,%1,%2,%3}, {%4,%5,%6,%7}, {%8,%9}, {%0,%1,%2,%3};\n"
        : "+f"(d[0]), "+f"(d[1]), "+f"(d[2]), "+f"(d[3])
        : "r"(a[0]), "r"(a[1]), "r"(a[2]), "r"(a[3]), "r"(b[0]), "r"(b[1]));
}

__device__ __forceinline__ void ldsm_x4(uint32_t& r0, uint32_t& r1, uint32_t& r2,
                                        uint32_t& r3, const __half* p) {
    uint32_t addr = (uint32_t)__cvta_generic_to_shared(p);
    asm volatile("ldmatrix.sync.aligned.m8n8.x4.shared.b16 {%0,%1,%2,%3}, [%4];"
                 : "=r"(r0), "=r"(r1), "=r"(r2), "=r"(r3) : "r"(addr));
}

// Batched fp32 -> fp16 convert: 5 (src,dst) pairs in one launch.
__global__ void __launch_bounds__(256)
cvt_all(const float4* __restrict__ s0, uint2* __restrict__ d0, int n0,
        const float4* __restrict__ s1, uint2* __restrict__ d1, int n1,
        const float4* __restrict__ s2, uint2* __restrict__ d2, int n2,
        const float4* __restrict__ s3, uint2* __restrict__ d3, int n3,
        const float4* __restrict__ s4, uint2* __restrict__ d4, int n4) {
    int i = blockIdx.x * blockDim.x + threadIdx.x;
    const float4* s;
    uint2* d;
    if (i < n0) { s = s0; d = d0; }
    else {
        i -= n0;
        if (i < n1) { s = s1; d = d1; }
        else {
            i -= n1;
            if (i < n2) { s = s2; d = d2; }
            else {
                i -= n2;
                if (i < n3) { s = s3; d = d3; }
                else {
                    i -= n3;
                    if (i >= n4) return;
                    s = s4; d = d4;
                }
            }
        }
    }
    float4 v = s[i];
    __half2 h01 = __floats2half2_rn(v.x, v.y);
    __half2 h23 = __floats2half2_rn(v.z, v.w);
    uint2 o;
    o.x = *reinterpret_cast<uint32_t*>(&h01);
    o.y = *reinterpret_cast<uint32_t*>(&h23);
    d[i] = o;
}

#define SH     72                  // smem row stride in halfwords (64 + 8 pad)
#define KSLAB  64                  // K elements per stage
#define STAGES 3
#define TILE_H (128 * SH)          // halfwords per matrix per stage (9216)
#define SMEM_BYTES (STAGES * 2 * TILE_H * 2)   // 110592

// C[M,N] = A[M,K] * B[N,K]^T. A,B fp16, C fp32, fp32 accumulate.
// Block tile 128x128xKSLAB, 128 thr = 4 warps of 64x64 (2M x 2N).
// 3-stage cp.async, 2 CTAs/SM (reg cap 256 via launch bounds).
// Two jobs packed into one grid: blocks [0,split) = job0, rest = job1.
__global__ void __launch_bounds__(128, 2)
gemm_fp16(const __half* __restrict__ A0, const __half* __restrict__ B0, float* __restrict__ C0,
          int N0,
          const __half* __restrict__ A1, const __half* __restrict__ B1, float* __restrict__ C1,
          int N1,
          int K, int split) {
    extern __shared__ __half smem[];
    __half* As = smem;                         // [STAGES][128][SH]
    __half* Bs = smem + STAGES * TILE_H;       // [STAGES][128][SH]

    const int tid  = threadIdx.x;
    const int lane = tid & 31;
    const int wid  = tid >> 5;
    const int wm   = wid & 1;                  // 2 M-warps (64 rows each)
    const int wn   = wid >> 1;                 // 2 N-warps (64 cols each)
    const int t    = lane & 3;
    const int g    = lane >> 2;

    // ldmatrix per-lane address components (fp16 m16n8k16 canonical)
    const int l_row = lane & 15;
    const int l_k   = (lane >> 4) * 8;         // 0 or 8 halfwords

    // job dispatch (bn fastest)
    const __half *A, *B;
    float* C;
    int N, bm, bn;
    if (blockIdx.x < split) {
        A = A0; B = B0; C = C0; N = N0;
        int nbx = N0 >> 7;
        bm = (blockIdx.x / nbx) << 7;
        bn = (blockIdx.x % nbx) << 7;
    } else {
        A = A1; B = B1; C = C1; N = N1;
        int idx = blockIdx.x - split;
        int nbx = N1 >> 7;
        bm = (idx / nbx) << 7;
        bn = (idx % nbx) << 7;
    }

    const __half* Ab = A + (size_t)bm * K;
    const __half* Bb = B + (size_t)bn * K;

    float acc[4][8][4];
#pragma unroll
    for (int mf = 0; mf < 4; mf++)
#pragma unroll
        for (int nf = 0; nf < 8; nf++)
#pragma unroll
            for (int i = 0; i < 4; i++) acc[mf][nf][i] = 0.f;

    // copy: 128 rows x 8 chunks(16B) per matrix = 1024 chunks; 8/thread each
#define ISSUE_TILE(st, kt)                                                           \
    do {                                                                             \
        const int _ko = (kt) * KSLAB;                                                \
        _Pragma("unroll")                                                            \
        for (int p = 0; p < 8; p++) {                                                \
            int c = tid + p * 128;                                                   \
            int row = c >> 3, cc = c & 7;                                            \
            uint32_t da = (uint32_t)__cvta_generic_to_shared(                        \
                As + (st) * TILE_H + row * SH + cc * 8);                             \
            const __half* ga = Ab + (size_t)row * K + _ko + cc * 8;                  \
            asm volatile("cp.async.cg.shared.global [%0], [%1], 16;\n"               \
                         :: "r"(da), "l"(ga));                                       \
            uint32_t db = (uint32_t)__cvta_generic_to_shared(                        \
                Bs + (st) * TILE_H + row * SH + cc * 8);                             \
            const __half* gb = Bb + (size_t)row * K + _ko + cc * 8;                  \
            asm volatile("cp.async.cg.shared.global [%0], [%1], 16;\n"               \
                         :: "r"(db), "l"(gb));                                       \
        }                                                                            \
    } while (0)

    ISSUE_TILE(0, 0);
    asm volatile("cp.async.commit_group;\n");
    ISSUE_TILE(1, 1);
    asm volatile("cp.async.commit_group;\n");

    const int KT = K / KSLAB;
    int cur = 0;
    for (int kt = 0; kt < KT; kt++) {
        asm volatile("cp.async.wait_group 1;\n");
        __syncthreads();

        if (kt + STAGES - 1 < KT) {
            int nst = cur + STAGES - 1;
            if (nst >= STAGES) nst -= STAGES;
            ISSUE_TILE(nst, kt + STAGES - 1);
        }
        asm volatile("cp.async.commit_group;\n");

        const __half* Ac = As + cur * TILE_H;
        const __half* Bc = Bs + cur * TILE_H;
#pragma unroll
        for (int s = 0; s < 4; s++) {               // 4 k16 steps per KSLAB=64
            const int kh = s * 16;
            uint32_t af[4][4], bf[8][2];
#pragma unroll
            for (int mf2 = 0; mf2 < 4; mf2++) {
                const __half* p = Ac + (wm * 64 + mf2 * 16 + l_row) * SH + kh + l_k;
                ldsm_x4(af[mf2][0], af[mf2][1], af[mf2][2], af[mf2][3], p);
            }
#pragma unroll
            for (int nf2 = 0; nf2 < 4; nf2++) {
                const __half* p = Bc + (wn * 64 + nf2 * 16 + l_row) * SH + kh + l_k;
                uint32_t r0, r1, r2, r3;
                ldsm_x4(r0, r1, r2, r3, p);
                bf[2 * nf2][0] = r0;     bf[2 * nf2][1] = r2;
                bf[2 * nf2 + 1][0] = r1; bf[2 * nf2 + 1][1] = r3;
            }
#pragma unroll
            for (int mf = 0; mf < 4; mf++)
#pragma unroll
                for (int nf = 0; nf < 8; nf++)
                    mma16(acc[mf][nf], af[mf], bf[nf]);
        }

        cur++;
        if (cur >= STAGES) cur = 0;
    }

    // epilogue
#pragma unroll
    for (int mf = 0; mf < 4; mf++) {
#pragma unroll
        for (int nf = 0; nf < 8; nf++) {
            int row = bm + wm * 64 + mf * 16 + g;
            int col = bn + wn * 64 + nf * 8 + t * 2;
            *(float2*)&C[(size_t)row * N + col] = make_float2(acc[mf][nf][0], acc[mf][nf][1]);
            *(float2*)&C[(size_t)(row + 8) * N + col] = make_float2(acc[mf][nf][2], acc[mf][nf][3]);
        }
    }
}

// One warp per (b, q, head). KW=4 lookback window, softmax over 4.
// Output converted to fp16 (feeds the Wo GEMM's A operand).
__global__ void __launch_bounds__(256)
attn_kernel(const float* __restrict__ qh, const float* __restrict__ kv,
            const int* __restrict__ seg, __half* __restrict__ out) {
    const int gw   = (blockIdx.x * blockDim.x + threadIdx.x) >> 5;
    const int lane = threadIdx.x & 31;
    const int h    = gw & (NHEADS - 1);
    const int qrow = gw >> 4;                // 0 .. NB*LQ-1
    const int b    = qrow >> 12;             // / LQ

    const int s = seg[qrow];

    const float* qp = qh + (size_t)qrow * DATTN + h * HDIM + lane * 2;
    const float2 qv = *(const float2*)qp;

    float  sc[4];
    float2 vv[4];
#pragma unroll
    for (int w = 0; w < 4; w++) {
        int idx = s - w;
        if (idx >= 0) {
            const float* kp = kv + (size_t)(b * LKV + idx) * (2 * DATTN) + h * HDIM + lane * 2;
            float2 kvv = *(const float2*)kp;
            vv[w] = *(const float2*)(kp + DATTN);
            float p = qv.x * kvv.x + qv.y * kvv.y;
#pragma unroll
            for (int o = 16; o > 0; o >>= 1) p += __shfl_xor_sync(0xffffffffu, p, o);
            sc[w] = p * 0.125f;              // HDIM^-0.5
        } else {
            sc[w] = -INFINITY;
            vv[w] = make_float2(0.f, 0.f);
        }
    }

    float m = fmaxf(fmaxf(sc[0], sc[1]), fmaxf(sc[2], sc[3]));
    float e[4], den = 0.f;
#pragma unroll
    for (int w = 0; w < 4; w++) { e[w] = __expf(sc[w] - m); den += e[w]; }
    const float r = 1.f / den;

    float2 o = make_float2(0.f, 0.f);
#pragma unroll
    for (int w = 0; w < 4; w++) {
        o.x += e[w] * r * vv[w].x;
        o.y += e[w] * r * vv[w].y;
    }
    __half2 oh = __floats2half2_rn(o.x, o.y);
    *(__half2*)(out + (size_t)qrow * DATTN + h * HDIM + lane * 2) = oh;
}

extern "C" void kernel_launch(void* const* d_in, const int* in_sizes, int n_in,
                              void* d_out, int out_size) {
    const float* q      = (const float*)d_in[0];
    const float* kv_src = (const float*)d_in[1];
    const int*   seg    = (const int*)d_in[2];
    const float* Wq     = (const float*)d_in[3];
    const float* Wkv    = (const float*)d_in[4];
    const float* Wo     = (const float*)d_in[5];
    float* out = (float*)d_out;

    float *qh, *kvb;
    __half *attn, *qr, *kvsr, *wq, *wkv, *wo;
    cudaGetSymbolAddress((void**)&qh,   g_qh);
    cudaGetSymbolAddress((void**)&kvb,  g_kv);
    cudaGetSymbolAddress((void**)&attn, g_attn);
    cudaGetSymbolAddress((void**)&qr,   g_qr);
    cudaGetSymbolAddress((void**)&kvsr, g_kvsr);
    cudaGetSymbolAddress((void**)&wq,   g_wq);
    cudaGetSymbolAddress((void**)&wkv,  g_wkv);
    cudaGetSymbolAddress((void**)&wo,   g_wo);

    cudaFuncSetAttribute(gemm_fp16, cudaFuncAttributeMaxDynamicSharedMemorySize, SMEM_BYTES);

    const int K = 1024;

    // convert all GEMM operands fp32 -> fp16 in ONE launch
    const int nq   = NB * LQ * 1024 / 4;
    const int nkvs = NB * LKV * 1024 / 4;
    const int nwq  = DATTN * 1024 / 4;
    const int nwkv = 2 * DATTN * 1024 / 4;
    const int nwo  = 1024 * DATTN / 4;
    const int ntot = nq + nkvs + nwq + nwkv + nwo;
    cvt_all<<<(ntot + 255) / 256, 256>>>(
        (const float4*)q, (uint2*)qr, nq,
        (const float4*)kv_src, (uint2*)kvsr, nkvs,
        (const float4*)Wq, (uint2*)wq, nwq,
        (const float4*)Wkv, (uint2*)wkv, nwkv,
        (const float4*)Wo, (uint2*)wo, nwo);

    // Job0: qh = q @ Wq^T (16384x1024) -> 1024 blocks
    // Job1: kv = kv_src @ Wkv^T (2048x2048) -> 256 blocks
    const int blocks0 = ((NB * LQ) >> 7) * (DATTN >> 7);
    const int blocks1 = ((NB * LKV) >> 7) * ((2 * DATTN) >> 7);
    gemm_fp16<<<blocks0 + blocks1, 128, SMEM_BYTES>>>(
        qr, wq, qh, DATTN,
        kvsr, wkv, kvb, 2 * DATTN,
        K, blocks0);

    // gathered windowed attention (fp32 in, fp16 out)
    attn_kernel<<<(NB * LQ * NHEADS * 32) / 256, 256>>>(qh, kvb, seg, attn);

    // out = attn @ Wo^T (16384 x 1024)
    gemm_fp16<<<blocks0, 128, SMEM_BYTES>>>(
        attn, wo, out, DATTN,
        attn, wo, out, DATTN,   // unused second job
        K, blocks0);
}